// round 1
// baseline (speedup 1.0000x reference)
#include <cuda_runtime.h>
#include <cuda_bf16.h>
#include <math.h>

// Problem constants
#define B_      4
#define T_      2048
#define KDIM    1024
#define HEADS   16
#define HDIM    64
#define ROWS    (B_ * T_)          // 8192
#define HALF    (KDIM / 2)         // 512

// ---------------------------------------------------------------------------
// Scratch (device globals: allocation-free per harness rules)
// ---------------------------------------------------------------------------
__device__ float g_q[ROWS * KDIM];
__device__ float g_k[ROWS * KDIM];
__device__ float g_v[ROWS * KDIM];
__device__ float g_a[ROWS * KDIM];

// ---------------------------------------------------------------------------
// GEMM: C[m][n] = sum_k A[m][k] * B[n][k]  (+ optional bias[n])
// A: [M][Kd] row-major, B: [N][Kd] row-major (i.e. C = A @ B^T)
// Tiles: 128x128x16, 256 threads, 8x8 per thread (quadrant split for LDS.128)
// ---------------------------------------------------------------------------
__global__ __launch_bounds__(256) void gemm_xt(
    const float* __restrict__ A, const float* __restrict__ B,
    const float* __restrict__ bias, float* __restrict__ C,
    int M, int N, int Kd)
{
    __shared__ float As[16][132];
    __shared__ float Bs[16][132];

    const int tid = threadIdx.x;
    const int tx = tid & 15;
    const int ty = tid >> 4;
    const int bm = blockIdx.y * 128;
    const int bn = blockIdx.x * 128;

    float acc[8][8];
#pragma unroll
    for (int i = 0; i < 8; i++)
#pragma unroll
        for (int j = 0; j < 8; j++) acc[i][j] = 0.0f;

    const int lr = tid >> 2;        // 0..63
    const int lk = (tid & 3) << 2;  // 0,4,8,12

    const float* Ap = A + (size_t)(bm + lr) * Kd + lk;
    const float* Bp = B + (size_t)(bn + lr) * Kd + lk;
    const size_t half_off = (size_t)64 * Kd;

    for (int k0 = 0; k0 < Kd; k0 += 16) {
        float4 a0 = *(const float4*)(Ap);
        float4 a1 = *(const float4*)(Ap + half_off);
        float4 b0 = *(const float4*)(Bp);
        float4 b1 = *(const float4*)(Bp + half_off);
        __syncthreads();
        As[lk + 0][lr] = a0.x; As[lk + 1][lr] = a0.y;
        As[lk + 2][lr] = a0.z; As[lk + 3][lr] = a0.w;
        As[lk + 0][64 + lr] = a1.x; As[lk + 1][64 + lr] = a1.y;
        As[lk + 2][64 + lr] = a1.z; As[lk + 3][64 + lr] = a1.w;
        Bs[lk + 0][lr] = b0.x; Bs[lk + 1][lr] = b0.y;
        Bs[lk + 2][lr] = b0.z; Bs[lk + 3][lr] = b0.w;
        Bs[lk + 0][64 + lr] = b1.x; Bs[lk + 1][64 + lr] = b1.y;
        Bs[lk + 2][64 + lr] = b1.z; Bs[lk + 3][64 + lr] = b1.w;
        __syncthreads();
#pragma unroll
        for (int kk = 0; kk < 16; kk++) {
            float4 af0 = *(const float4*)&As[kk][ty * 4];
            float4 af1 = *(const float4*)&As[kk][64 + ty * 4];
            float4 bf0 = *(const float4*)&Bs[kk][tx * 4];
            float4 bf1 = *(const float4*)&Bs[kk][64 + tx * 4];
            float a_[8] = {af0.x, af0.y, af0.z, af0.w, af1.x, af1.y, af1.z, af1.w};
            float b_[8] = {bf0.x, bf0.y, bf0.z, bf0.w, bf1.x, bf1.y, bf1.z, bf1.w};
#pragma unroll
            for (int i = 0; i < 8; i++)
#pragma unroll
                for (int j = 0; j < 8; j++)
                    acc[i][j] = fmaf(a_[i], b_[j], acc[i][j]);
        }
        Ap += 16;
        Bp += 16;
    }

#pragma unroll
    for (int i = 0; i < 8; i++) {
        int r = bm + ((i < 4) ? (ty * 4 + i) : (64 + ty * 4 + i - 4));
#pragma unroll
        for (int jh = 0; jh < 2; jh++) {
            int c = bn + (jh ? (64 + tx * 4) : (tx * 4));
            float4 v;
            v.x = acc[i][jh * 4 + 0];
            v.y = acc[i][jh * 4 + 1];
            v.z = acc[i][jh * 4 + 2];
            v.w = acc[i][jh * 4 + 3];
            if (bias) {
                v.x += bias[c + 0]; v.y += bias[c + 1];
                v.z += bias[c + 2]; v.w += bias[c + 3];
            }
            *(float4*)&C[(size_t)r * N + c] = v;
        }
    }
}

// ---------------------------------------------------------------------------
// RoPE applied in-place to Q and K over the full 1024-dim channel.
// One thread per (row, pair). idx = bt*HALF + j; pair = channels (2j, 2j+1).
// ---------------------------------------------------------------------------
__global__ void rope_kernel(float* __restrict__ Q, float* __restrict__ K, int total)
{
    int idx = blockIdx.x * blockDim.x + threadIdx.x;
    if (idx >= total) return;
    int j = idx % HALF;
    int t = (idx / HALF) % T_;
    float theta = powf(10000.0f, -(float)j / (float)HALF);
    float ang = (float)t * theta;
    float s, c;
    sincosf(ang, &s, &c);

    float2* q2 = (float2*)Q;
    float2* k2 = (float2*)K;
    float2 q = q2[idx];
    float2 k = k2[idx];
    q2[idx] = make_float2(q.x * c - q.y * s, q.x * s + q.y * c);
    k2[idx] = make_float2(k.x * c - k.y * s, k.x * s + k.y * c);
}

// ---------------------------------------------------------------------------
// Flash attention (fp32 SIMT). One CTA = (64 q-rows) x (one batch*head).
// 128 threads: thread grid 8 (row-groups) x 16 (col-groups).
// Per key-iter BN=64: S = Q K^T -> online softmax -> P through smem -> O += P V.
// Row stats reduced across the 16 lanes owning each row via shfl_xor (<=8).
// ---------------------------------------------------------------------------
#define ASTR 68   // smem row stride (floats): 16B-aligned, conflict-mitigating

__global__ __launch_bounds__(128) void attn_kernel(
    const float* __restrict__ Q, const float* __restrict__ K,
    const float* __restrict__ V, float* __restrict__ O)
{
    extern __shared__ float sm[];
    float (*Qs)[ASTR] = (float(*)[ASTR])(sm);               // Qs[d][r]
    float (*Ks)[ASTR] = (float(*)[ASTR])(sm + 64 * ASTR);   // Ks[d][c]
    float (*Vs)[ASTR] = (float(*)[ASTR])(sm + 2 * 64 * ASTR); // Vs[c][d]
    float (*Ps)[ASTR] = (float(*)[ASTR])(sm + 3 * 64 * ASTR); // Ps[c][r]

    const int tid = threadIdx.x;
    const int tcol = tid & 15;   // 16 column-groups (4 cols each)
    const int trow = tid >> 4;   // 8 row-groups
    const int qtile = blockIdx.x;       // 0..31
    const int bh = blockIdx.y;          // 0..63
    const int b = bh >> 4;
    const int h = bh & 15;
    const size_t rowbase = (size_t)b * T_;
    const int colbase = h * HDIM;

    int rI[8];
#pragma unroll
    for (int i = 0; i < 8; i++)
        rI[i] = (i < 4) ? (trow * 4 + i) : (32 + trow * 4 + i - 4);

    // Load Q tile [64 rows x 64 dims], transposed into Qs[d][r]
    {
        const int d0 = (tid & 15) * 4;
        const int r0 = tid >> 4;
#pragma unroll
        for (int p = 0; p < 8; p++) {
            int r = p * 8 + r0;
            float4 v = *(const float4*)&Q[(rowbase + qtile * 64 + r) * KDIM + colbase + d0];
            Qs[d0 + 0][r] = v.x; Qs[d0 + 1][r] = v.y;
            Qs[d0 + 2][r] = v.z; Qs[d0 + 3][r] = v.w;
        }
    }

    float m[8], l[8], o[8][4];
#pragma unroll
    for (int i = 0; i < 8; i++) {
        m[i] = -1e30f;
        l[i] = 0.0f;
#pragma unroll
        for (int j = 0; j < 4; j++) o[i][j] = 0.0f;
    }

    for (int kt = 0; kt < T_ / 64; kt++) {
        __syncthreads();  // previous iter's reads of Ks/Vs done
        // Load K tile (transposed -> Ks[d][c]) and V tile (natural -> Vs[c][d])
        {
            const int d0 = (tid & 15) * 4;
            const int r0 = tid >> 4;
#pragma unroll
            for (int p = 0; p < 8; p++) {
                int r = p * 8 + r0;
                size_t gro = (rowbase + kt * 64 + r) * KDIM + colbase + d0;
                float4 kv = *(const float4*)&K[gro];
                Ks[d0 + 0][r] = kv.x; Ks[d0 + 1][r] = kv.y;
                Ks[d0 + 2][r] = kv.z; Ks[d0 + 3][r] = kv.w;
                float4 vv = *(const float4*)&V[gro];
                *(float4*)&Vs[r][d0] = vv;
            }
        }
        __syncthreads();

        // S = Q K^T for this tile: thread computes s[8 rows][4 cols]
        float s[8][4];
#pragma unroll
        for (int i = 0; i < 8; i++)
#pragma unroll
            for (int j = 0; j < 4; j++) s[i][j] = 0.0f;

#pragma unroll 4
        for (int d = 0; d < 64; d++) {
            float4 q0 = *(const float4*)&Qs[d][trow * 4];
            float4 q1 = *(const float4*)&Qs[d][32 + trow * 4];
            float4 kf = *(const float4*)&Ks[d][tcol * 4];
            float qv[8] = {q0.x, q0.y, q0.z, q0.w, q1.x, q1.y, q1.z, q1.w};
            float kv[4] = {kf.x, kf.y, kf.z, kf.w};
#pragma unroll
            for (int i = 0; i < 8; i++)
#pragma unroll
                for (int j = 0; j < 4; j++)
                    s[i][j] = fmaf(qv[i], kv[j], s[i][j]);
        }
#pragma unroll
        for (int i = 0; i < 8; i++)
#pragma unroll
            for (int j = 0; j < 4; j++) s[i][j] *= 0.125f;  // 1/sqrt(64)

        // Online softmax update; write P to smem
#pragma unroll
        for (int i = 0; i < 8; i++) {
            float mx = fmaxf(fmaxf(s[i][0], s[i][1]), fmaxf(s[i][2], s[i][3]));
#pragma unroll
            for (int off = 8; off >= 1; off >>= 1)
                mx = fmaxf(mx, __shfl_xor_sync(0xffffffffu, mx, off));
            float mnew = fmaxf(m[i], mx);
            float corr = __expf(m[i] - mnew);
            float rs = 0.0f;
#pragma unroll
            for (int j = 0; j < 4; j++) {
                float p = __expf(s[i][j] - mnew);
                Ps[tcol * 4 + j][rI[i]] = p;
                rs += p;
            }
#pragma unroll
            for (int off = 8; off >= 1; off >>= 1)
                rs += __shfl_xor_sync(0xffffffffu, rs, off);
            l[i] = l[i] * corr + rs;
#pragma unroll
            for (int j = 0; j < 4; j++) o[i][j] *= corr;
            m[i] = mnew;
        }
        __syncthreads();  // P visible to all

        // O += P V : thread accumulates o[8 rows][4 dims], dims = tcol*4..
#pragma unroll 4
        for (int c = 0; c < 64; c++) {
            float4 p0 = *(const float4*)&Ps[c][trow * 4];
            float4 p1 = *(const float4*)&Ps[c][32 + trow * 4];
            float4 vf = *(const float4*)&Vs[c][tcol * 4];
            float pv[8] = {p0.x, p0.y, p0.z, p0.w, p1.x, p1.y, p1.z, p1.w};
            float vv[4] = {vf.x, vf.y, vf.z, vf.w};
#pragma unroll
            for (int i = 0; i < 8; i++)
#pragma unroll
                for (int j = 0; j < 4; j++)
                    o[i][j] = fmaf(pv[i], vv[j], o[i][j]);
        }
    }

    // Normalize and write out (layout [b*t][h*64])
#pragma unroll
    for (int i = 0; i < 8; i++) {
        float inv = 1.0f / l[i];
        float4 w = make_float4(o[i][0] * inv, o[i][1] * inv, o[i][2] * inv, o[i][3] * inv);
        *(float4*)&O[(rowbase + qtile * 64 + rI[i]) * KDIM + colbase + tcol * 4] = w;
    }
}

// ---------------------------------------------------------------------------
// Launcher
// ---------------------------------------------------------------------------
extern "C" void kernel_launch(void* const* d_in, const int* in_sizes, int n_in,
                              void* d_out, int out_size)
{
    const float* x  = (const float*)d_in[0];
    const float* Wq = (const float*)d_in[1];
    const float* Wk = (const float*)d_in[2];
    const float* Wv = (const float*)d_in[3];
    const float* Wu = (const float*)d_in[4];
    const float* bu = (const float*)d_in[5];
    float* out = (float*)d_out;

    float *q, *k, *v, *a;
    cudaGetSymbolAddress((void**)&q, g_q);
    cudaGetSymbolAddress((void**)&k, g_k);
    cudaGetSymbolAddress((void**)&v, g_v);
    cudaGetSymbolAddress((void**)&a, g_a);

    dim3 ggrid(KDIM / 128, ROWS / 128);  // (8, 64)

    // QKV projections
    gemm_xt<<<ggrid, 256>>>(x, Wq, nullptr, q, ROWS, KDIM, KDIM);
    gemm_xt<<<ggrid, 256>>>(x, Wk, nullptr, k, ROWS, KDIM, KDIM);
    gemm_xt<<<ggrid, 256>>>(x, Wv, nullptr, v, ROWS, KDIM, KDIM);

    // RoPE on Q, K (in place)
    int total_pairs = ROWS * HALF;
    rope_kernel<<<(total_pairs + 255) / 256, 256>>>(q, k, total_pairs);

    // Attention
    int attn_smem = 4 * 64 * ASTR * (int)sizeof(float);  // 69632 B
    cudaFuncSetAttribute(attn_kernel, cudaFuncAttributeMaxDynamicSharedMemorySize, attn_smem);
    attn_kernel<<<dim3(T_ / 64, B_ * HEADS), 128, attn_smem>>>(q, k, v, a);

    // Output projection + bias
    gemm_xt<<<ggrid, 256>>>(a, Wu, bu, out, ROWS, KDIM, KDIM);
}